// round 3
// baseline (speedup 1.0000x reference)
#include <cuda_runtime.h>

#define NN 100000
#define NE 1600000

// Scratch slots, each NN*64 floats (25.6MB): 0..3
__device__ float g_scratch[4ull * NN * 64];
__device__ float g_dinv[NN];
__device__ int g_deg[NN];      // int in-degree
__device__ int g_rowptr[NN];   // exclusive prefix sum of deg
__device__ int g_fill[NN];     // fill cursors (init = rowptr)
__device__ int g_adj[NE];      // src ids grouped by dst
__device__ int g_is64;

// A_j = sum_s T[s][j] * Wm1_s  with T = THETAS matrix for D=2
__constant__ float COEF[3][3] = {
    {3.0f,  0.0f,  0.0f},
    {-3.0f, 3.0f,  0.0f},
    {0.75f, -1.5f, 0.75f}
};

__device__ __forceinline__ float* slot(int s) {
    return g_scratch + (size_t)s * (NN * 64);
}

// ---------------------------------------------------------------------------
// Zero degree counters; thread (0,0) also detects edge_index dtype.
// int64 data: every 8-byte word has high half == 0 (indices < 1e5).
__global__ void zero_detect_kernel(const void* ei) {
    int i = blockIdx.x * 256 + threadIdx.x;
    if (i < NN) g_deg[i] = 0;
    if (i == 0) {
        const unsigned long long* p = (const unsigned long long*)ei;
        int is64 = 1;
        for (int k = 0; k < 64; k++)
            if ((p[k] >> 32) != 0ull) { is64 = 0; break; }
        g_is64 = is64;
    }
}

__global__ void count_kernel(const void* ei) {
    int e = blockIdx.x * 256 + threadIdx.x;
    if (e < NE) {
        int d = g_is64 ? (int)((const long long*)ei)[NE + e]
                       : ((const int*)ei)[NE + e];
        atomicAdd(&g_deg[d], 1);
    }
}

// Single-block exclusive scan over NN degrees -> rowptr, fill, dinv.
__global__ __launch_bounds__(1024)
void scan_kernel() {
    __shared__ int sums[1024];
    int t = threadIdx.x;
    const int CH = (NN + 1023) / 1024;  // 98
    int beg = t * CH;
    int end = beg + CH; if (end > NN) end = NN;
    int s = 0;
    for (int i = beg; i < end; i++) s += g_deg[i];
    sums[t] = s;
    __syncthreads();
    for (int off = 1; off < 1024; off <<= 1) {
        int v = (t >= off) ? sums[t - off] : 0;
        __syncthreads();
        sums[t] += v;
        __syncthreads();
    }
    int run = t ? sums[t - 1] : 0;
    for (int i = beg; i < end; i++) {
        int d = g_deg[i];
        g_rowptr[i] = run;
        g_fill[i] = run;
        g_dinv[i] = rsqrtf((float)(d > 0 ? d : 1));
        run += d;
    }
}

__global__ void fill_kernel(const void* ei) {
    int e = blockIdx.x * 256 + threadIdx.x;
    if (e < NE) {
        int s, d;
        if (g_is64) {
            const long long* p = (const long long*)ei;
            s = (int)p[e]; d = (int)p[NE + e];
        } else {
            const int* p = (const int*)ei;
            s = p[e]; d = p[NE + e];
        }
        int pos = atomicAdd(&g_fill[d], 1);
        g_adj[pos] = s;
    }
}

// ---------------------------------------------------------------------------
// Y[N,64] = relu(X[N,K] @ W[K,64] + B); optionally also G = Y * dinv (fused prep)
template <int K, bool WRITE_G>
__global__ __launch_bounds__(256)
void gemm_relu_kernel(const float* __restrict__ Xext, int xslot,
                      const float* __restrict__ W, const float* __restrict__ B,
                      int yslot, int gslot) {
    const float* X = Xext ? Xext : slot(xslot);
    float* Y = slot(yslot);

    __shared__ float xs[64 * 68];  // transposed: xs[k][node], stride 68
    __shared__ float ws[64 * 64];  // ws[k][col]

    int tid = threadIdx.x;
    int tx = tid & 15, ty = tid >> 4;
    int nodeBase = blockIdx.x * 64;

    float acc[4][4];
#pragma unroll
    for (int i = 0; i < 4; i++)
#pragma unroll
        for (int j = 0; j < 4; j++) acc[i][j] = 0.0f;

    for (int kc = 0; kc < K; kc += 64) {
#pragma unroll
        for (int i = 0; i < 4; i++) {
            int p = i * 256 + tid;
            int r = p >> 4;
            int c4 = p & 15;
            int node = nodeBase + r;
            float4 v = make_float4(0.f, 0.f, 0.f, 0.f);
            if (node < NN)
                v = *(const float4*)(X + (size_t)node * K + kc + c4 * 4);
            int k0 = c4 * 4;
            xs[(k0 + 0) * 68 + r] = v.x;
            xs[(k0 + 1) * 68 + r] = v.y;
            xs[(k0 + 2) * 68 + r] = v.z;
            xs[(k0 + 3) * 68 + r] = v.w;
        }
#pragma unroll
        for (int i = 0; i < 4; i++) {
            int p = i * 256 + tid;
            ((float4*)ws)[p] =
                *(const float4*)(W + (size_t)(kc + (p >> 4)) * 64 + (p & 15) * 4);
        }
        __syncthreads();
#pragma unroll
        for (int k = 0; k < 64; k++) {
            float4 a = *(float4*)&xs[k * 68 + ty * 4];
            float4 b = *(float4*)&ws[k * 64 + tx * 4];
            acc[0][0] += a.x * b.x; acc[0][1] += a.x * b.y; acc[0][2] += a.x * b.z; acc[0][3] += a.x * b.w;
            acc[1][0] += a.y * b.x; acc[1][1] += a.y * b.y; acc[1][2] += a.y * b.z; acc[1][3] += a.y * b.w;
            acc[2][0] += a.z * b.x; acc[2][1] += a.z * b.y; acc[2][2] += a.z * b.z; acc[2][3] += a.z * b.w;
            acc[3][0] += a.w * b.x; acc[3][1] += a.w * b.y; acc[3][2] += a.w * b.z; acc[3][3] += a.w * b.w;
        }
        __syncthreads();
    }

    float4 bb = *(const float4*)&B[tx * 4];
#pragma unroll
    for (int i = 0; i < 4; i++) {
        int node = nodeBase + ty * 4 + i;
        if (node < NN) {
            float4 o;
            o.x = fmaxf(acc[i][0] + bb.x, 0.0f);
            o.y = fmaxf(acc[i][1] + bb.y, 0.0f);
            o.z = fmaxf(acc[i][2] + bb.z, 0.0f);
            o.w = fmaxf(acc[i][3] + bb.w, 0.0f);
            *(float4*)(Y + (size_t)node * 64 + tx * 4) = o;
            if (WRITE_G) {
                float di = g_dinv[node];
                float4 gv = make_float4(o.x * di, o.y * di, o.z * di, o.w * di);
                *(float4*)(slot(gslot) + (size_t)node * 64 + tx * 4) = gv;
            }
        }
    }
}

// ---------------------------------------------------------------------------
// CSR gather: msg[d] = sum over in-edges of g[src]. 16 lanes per node,
// 16 nodes per 256-thread block. Writes each row exactly once (no atomics).
__global__ __launch_bounds__(256)
void gather_kernel(int gslot, int mslot) {
    const float4* g = (const float4*)slot(gslot);
    float4* msg = (float4*)slot(mslot);

    int node = blockIdx.x * 16 + (threadIdx.x >> 4);
    int lane = threadIdx.x & 15;

    int beg = g_rowptr[node];
    int end = beg + g_deg[node];

    float4 acc = make_float4(0.f, 0.f, 0.f, 0.f);
    int j = beg;
    for (; j + 4 <= end; j += 4) {
        int s0 = g_adj[j + 0];
        int s1 = g_adj[j + 1];
        int s2 = g_adj[j + 2];
        int s3 = g_adj[j + 3];
        float4 v0 = g[(size_t)s0 * 16 + lane];
        float4 v1 = g[(size_t)s1 * 16 + lane];
        float4 v2 = g[(size_t)s2 * 16 + lane];
        float4 v3 = g[(size_t)s3 * 16 + lane];
        acc.x += v0.x; acc.y += v0.y; acc.z += v0.z; acc.w += v0.w;
        acc.x += v1.x; acc.y += v1.y; acc.z += v1.z; acc.w += v1.w;
        acc.x += v2.x; acc.y += v2.y; acc.z += v2.z; acc.w += v2.w;
        acc.x += v3.x; acc.y += v3.y; acc.z += v3.z; acc.w += v3.w;
    }
    for (; j < end; j++) {
        int s = g_adj[j];
        float4 v = g[(size_t)s * 16 + lane];
        acc.x += v.x; acc.y += v.y; acc.z += v.z; acc.w += v.w;
    }
    msg[(size_t)node * 16 + lane] = acc;
}

// ---------------------------------------------------------------------------
// f1 = f0 - msg*dinv ; g = f1*dinv
__global__ __launch_bounds__(256)
void update_kernel(int f0slot, int msgslot, int f1slot, int gslot) {
    int i = blockIdx.x * 256 + threadIdx.x;
    if (i < NN * 16) {
        const float4* f0 = (const float4*)slot(f0slot);
        const float4* msg = (const float4*)slot(msgslot);
        float4* f1 = (float4*)slot(f1slot);
        float4* g = (float4*)slot(gslot);
        float di = g_dinv[i >> 4];
        float4 a = f0[i], m = msg[i];
        float4 f;
        f.x = a.x - m.x * di;
        f.y = a.y - m.y * di;
        f.z = a.z - m.z * di;
        f.w = a.w - m.w * di;
        f1[i] = f;
        g[i] = make_float4(f.x * di, f.y * di, f.z * di, f.w * di);
    }
}

// ---------------------------------------------------------------------------
// Final: f2 = f1 - msg*dinv (on the fly); hf = relu(sum_j f_j @ A_j + bm1);
// out = hf @ Wm2 + bm2.
__global__ __launch_bounds__(256)
void final_kernel(int f0slot, int f1slot, int msgslot,
                  const float* __restrict__ Wm1, const float* __restrict__ bm1,
                  const float* __restrict__ Wm2, const float* __restrict__ bm2,
                  float* __restrict__ out) {
    const float4* f0 = (const float4*)slot(f0slot);
    const float4* f1 = (const float4*)slot(f1slot);
    const float4* msg = (const float4*)slot(msgslot);

    __shared__ float fs[64 * 68];  // transposed f tile, later reused as hf
    __shared__ float as[64 * 64];  // A_j[k][col]
    __shared__ float wm2s[128];

    int tid = threadIdx.x;
    int tx = tid & 15, ty = tid >> 4;
    int nodeBase = blockIdx.x * 64;

    if (tid < 128) wm2s[tid] = Wm2[tid];

    float acc[4][4];
#pragma unroll
    for (int i = 0; i < 4; i++)
#pragma unroll
        for (int j = 0; j < 4; j++) acc[i][j] = 0.0f;

    const float4* Wm1_4 = (const float4*)Wm1;

    for (int j = 0; j < 3; j++) {
        float c0 = COEF[j][0], c1 = COEF[j][1], c2 = COEF[j][2];
#pragma unroll
        for (int i = 0; i < 4; i++) {
            int p = i * 256 + tid;
            float4 w0 = Wm1_4[p];
            float4 w1 = Wm1_4[1024 + p];
            float4 w2 = Wm1_4[2048 + p];
            float4 a;
            a.x = c0 * w0.x + c1 * w1.x + c2 * w2.x;
            a.y = c0 * w0.y + c1 * w1.y + c2 * w2.y;
            a.z = c0 * w0.z + c1 * w1.z + c2 * w2.z;
            a.w = c0 * w0.w + c1 * w1.w + c2 * w2.w;
            ((float4*)as)[p] = a;
        }
#pragma unroll
        for (int i = 0; i < 4; i++) {
            int p = i * 256 + tid;
            int r = p >> 4, c4 = p & 15;
            int node = nodeBase + r;
            float4 v = make_float4(0.f, 0.f, 0.f, 0.f);
            if (node < NN) {
                int idx = node * 16 + c4;
                if (j == 0) {
                    v = f0[idx];
                } else if (j == 1) {
                    v = f1[idx];
                } else {
                    float4 a1 = f1[idx], m = msg[idx];
                    float di = g_dinv[node];
                    v.x = a1.x - m.x * di;
                    v.y = a1.y - m.y * di;
                    v.z = a1.z - m.z * di;
                    v.w = a1.w - m.w * di;
                }
            }
            int k0 = c4 * 4;
            fs[(k0 + 0) * 68 + r] = v.x;
            fs[(k0 + 1) * 68 + r] = v.y;
            fs[(k0 + 2) * 68 + r] = v.z;
            fs[(k0 + 3) * 68 + r] = v.w;
        }
        __syncthreads();
#pragma unroll
        for (int k = 0; k < 64; k++) {
            float4 a = *(float4*)&fs[k * 68 + ty * 4];
            float4 b = *(float4*)&as[k * 64 + tx * 4];
            acc[0][0] += a.x * b.x; acc[0][1] += a.x * b.y; acc[0][2] += a.x * b.z; acc[0][3] += a.x * b.w;
            acc[1][0] += a.y * b.x; acc[1][1] += a.y * b.y; acc[1][2] += a.y * b.z; acc[1][3] += a.y * b.w;
            acc[2][0] += a.z * b.x; acc[2][1] += a.z * b.y; acc[2][2] += a.z * b.z; acc[2][3] += a.z * b.w;
            acc[3][0] += a.w * b.x; acc[3][1] += a.w * b.y; acc[3][2] += a.w * b.z; acc[3][3] += a.w * b.w;
        }
        __syncthreads();
    }

    float4 bb = *(const float4*)&bm1[tx * 4];
#pragma unroll
    for (int i = 0; i < 4; i++) {
        int r = ty * 4 + i;
        float4 o;
        o.x = fmaxf(acc[i][0] + bb.x, 0.0f);
        o.y = fmaxf(acc[i][1] + bb.y, 0.0f);
        o.z = fmaxf(acc[i][2] + bb.z, 0.0f);
        o.w = fmaxf(acc[i][3] + bb.w, 0.0f);
        *(float4*)&fs[r * 68 + tx * 4] = o;
    }
    __syncthreads();

    if (tid < 128) {
        int n = tid >> 1, c = tid & 1;
        int node = nodeBase + n;
        if (node < NN) {
            float s = bm2[c];
#pragma unroll
            for (int k = 0; k < 64; k++) s += fs[n * 68 + k] * wm2s[k * 2 + c];
            out[(size_t)node * 2 + c] = s;
        }
    }
}

// ---------------------------------------------------------------------------
extern "C" void kernel_launch(void* const* d_in, const int* in_sizes, int n_in,
                              void* d_out, int out_size) {
    const float* x = (const float*)d_in[0];
    const void* ei = d_in[1];
    const float* W1 = (const float*)d_in[2];
    const float* b1 = (const float*)d_in[3];
    const float* W2 = (const float*)d_in[4];
    const float* b2 = (const float*)d_in[5];
    const float* Wm1 = (const float*)d_in[6];
    const float* bm1 = (const float*)d_in[7];
    const float* Wm2 = (const float*)d_in[8];
    const float* bm2 = (const float*)d_in[9];
    float* out = (float*)d_out;

    int nbn = (NN + 255) / 256;
    int nbe = (NE + 255) / 256;

    // CSR build
    zero_detect_kernel<<<nbn, 256>>>(ei);
    count_kernel<<<nbe, 256>>>(ei);
    scan_kernel<<<1, 1024>>>();
    fill_kernel<<<nbe, 256>>>(ei);

    int nb = (NN + 63) / 64;  // 1563
    // h1 = relu(x @ W1 + b1)                    -> slot 0
    gemm_relu_kernel<128, false><<<nb, 256>>>(x, -1, W1, b1, 0, -1);
    // f0 = relu(h1 @ W2 + b2) -> slot 1 ; g = f0*dinv -> slot 2 (fused prep)
    gemm_relu_kernel<64, true><<<nb, 256>>>(nullptr, 0, W2, b2, 1, 2);

    int nv = (NN * 16 + 255) / 256;
    int ng = NN / 16;  // 6250, exact

    // pass 1: msg(slot3) = gather(g)
    gather_kernel<<<ng, 256>>>(2, 3);
    // f1(slot0) = f0 - msg*dinv ; g(slot2) = f1*dinv
    update_kernel<<<nv, 256>>>(1, 3, 0, 2);
    // pass 2: msg(slot3) = gather(g)
    gather_kernel<<<ng, 256>>>(2, 3);

    // final fused MLP (f2 computed on the fly from f1, msg)
    final_kernel<<<nb, 256>>>(1, 0, 3, Wm1, bm1, Wm2, bm2, out);
}